// round 13
// baseline (speedup 1.0000x reference)
#include <cuda_runtime.h>
#include <cstdint>

// Problem constants (fixed by dataset: B=16, H=1024, W=2048, G=8, C=19)
#define NB      524288
#define NC      19
#define WID     2048
#define HEI     1024
#define GS      8
#define BLOCKS_PER_TILE 64                     // quarter block-row
#define NTILES  (NB/BLOCKS_PER_TILE)           // 8192
#define TGT_ROW_BYTES 2048                     // 512 px * 4B per strip row
#define TGT_BYTES (8*TGT_ROW_BYTES)            // 16384
#define PRED_BYTES (BLOCKS_PER_TILE*NC*4)      // 4864 (16B multiple)
#define STAGE_BYTES (TGT_BYTES + PRED_BYTES)   // 21248
#define NSTAGE  4
#define GRID    304                            // 2 CTAs per SM (152 SMs)
#define V_PER_TILE (BLOCKS_PER_TILE*NC/4)      // 304 float4

// Allocation-free scratch (__device__ globals per harness rules)
__device__ double       g_partials[GRID];
__device__ unsigned int g_count = 0;           // self-resetting completion counter

// Numerically stable softplus: max(x,0) + log(1 + exp(-|x|))
__device__ __forceinline__ float softplus_f(float x)
{
    float e = __expf(-fabsf(x));
    return fmaxf(x, 0.0f) + __logf(1.0f + e);
}

__device__ __forceinline__ void mbar_init(uint32_t mbar, unsigned count)
{
    asm volatile("mbarrier.init.shared.b64 [%0], %1;" :: "r"(mbar), "r"(count) : "memory");
}

__device__ __forceinline__ void mbar_wait(uint32_t mbar, unsigned phase)
{
    asm volatile(
        "{\n\t.reg .pred P;\n\t"
        "WAIT_%=:\n\t"
        "mbarrier.try_wait.parity.acquire.cta.shared::cta.b64 P, [%0], %1, 0x989680;\n\t"
        "@P bra DONE_%=;\n\t"
        "bra WAIT_%=;\n\t"
        "DONE_%=:\n\t}"
        :: "r"(mbar), "r"(phase) : "memory");
}

__device__ __forceinline__ void bulk_cp(uint32_t dst_smem, const void* src,
                                        unsigned bytes, uint32_t mbar)
{
    asm volatile(
        "cp.async.bulk.shared::cluster.global.mbarrier::complete_tx::bytes "
        "[%0], [%1], %2, [%3];"
        :: "r"(dst_smem), "l"(src), "r"(bytes), "r"(mbar) : "memory");
}

// Issue one tile's loads: expect_tx + 8 target-row copies + 1 preds copy.
__device__ __forceinline__ void issue_tile(const int* tgt, const float* preds,
                                           unsigned tile, uint32_t stage, uint32_t mbar)
{
    asm volatile("mbarrier.arrive.expect_tx.shared.b64 _, [%0], %1;"
                 :: "r"(mbar), "r"((unsigned)STAGE_BYTES) : "memory");
    unsigned qtr  = tile & 3u;                  // quarter of the block-row
    unsigned bh   = (tile >> 2) & 127u;
    unsigned bimg = tile >> 9;
    const char* tsrc = (const char*)(tgt
        + ((size_t)(bimg * HEI + bh * GS)) * WID + (size_t)qtr * 512u);
#pragma unroll
    for (int r = 0; r < 8; r++)
        bulk_cp(stage + r * TGT_ROW_BYTES, tsrc + (size_t)r * WID * 4,
                TGT_ROW_BYTES, mbar);
    bulk_cp(stage + TGT_BYTES, (const char*)preds + (size_t)tile * PRED_BYTES,
            PRED_BYTES, mbar);
}

// ---------------------------------------------------------------------------
// TMA 4-stage pipelined fused kernel. 304 CTAs, static tile assignment.
// Up to 3 tiles in flight per CTA while the 4th is consumed -> TMA engine
// never drains during the compute/barrier window.
// ---------------------------------------------------------------------------
__global__ void __launch_bounds__(256)
fused_kernel(const int*   __restrict__ tgt,
             const float* __restrict__ preds,
             float*       __restrict__ out)
{
    extern __shared__ char stage_mem[];                 // NSTAGE * STAGE_BYTES
    __shared__ unsigned long long mbar_store[NSTAGE];
    __shared__ unsigned int sm_mask[BLOCKS_PER_TILE + 1];
    __shared__ float  ws[8];
    __shared__ double sh[256];

    const unsigned tid  = threadIdx.x;
    const unsigned lane = tid & 31u;
    const unsigned wix  = tid >> 5;
    const unsigned cta  = blockIdx.x;

    const uint32_t stage0 = (uint32_t)__cvta_generic_to_shared(stage_mem);
    const uint32_t mbb    = (uint32_t)__cvta_generic_to_shared(&mbar_store[0]);

    if (tid == 0) {
#pragma unroll
        for (int k = 0; k < NSTAGE; k++) mbar_init(mbb + 8u * k, 1);
        asm volatile("fence.proxy.async.shared::cta;" ::: "memory");
        // Prologue: fill all stages (every CTA has >= 26 tiles)
#pragma unroll
        for (unsigned k = 0; k < NSTAGE; k++)
            issue_tile(tgt, preds, cta + k * GRID,
                       stage0 + k * STAGE_BYTES, mbb + 8u * k);
    }
    __syncthreads();

    float s = 0.0f;
    unsigned n = 0;

    for (unsigned tile = cta; tile < NTILES; tile += GRID, n++) {
        const unsigned k = n & (NSTAGE - 1u);
        const uint32_t  stg  = stage0 + k * STAGE_BYTES;
        const char*     stgp = stage_mem + (size_t)k * STAGE_BYTES;
        const uint32_t  mb   = mbb + 8u * k;
        const unsigned  ph   = (n >> 2) & 1u;   // stage reused every 4 iters

        mbar_wait(mb, ph);

        // ---- masks: 128 threads, pair (2p,2p+1) covers block p's halves ----
        // Quarter-warp phases hit 8 distinct (p mod 4, h) bank groups: no conflicts.
        if (tid < 2u * BLOCKS_PER_TILE) {
            unsigned p = tid >> 1, h = tid & 1u;
            unsigned m = 0u;
#pragma unroll
            for (int r = 0; r < 8; r++) {
                int4 v = *(const int4*)(stgp + r * TGT_ROW_BYTES + p * 32u + h * 16u);
                m |= (1u << v.x) | (1u << v.y) | (1u << v.z) | (1u << v.w);
            }
            m |= __shfl_xor_sync(0xffffffffu, m, 1);
            if (h == 0u) sm_mask[p] = m;
            if (tid == 0u) sm_mask[BLOCKS_PER_TILE] = 0u;
        }
        __syncthreads();                 // masks visible

        // ---- preds: 304 float4 from smem, softplus + correction ----
        const float4* pvs = (const float4*)(stgp + TGT_BYTES);
#pragma unroll
        for (int it = 0; it < 2; it++) {
            unsigned j = tid + (unsigned)it * 256u;
            if (it == 1 && tid >= (V_PER_TILE - 256)) break;   // tail: tid < 48
            unsigned e0 = j * 4u;
            unsigned q  = e0 / 19u;                 // 0..63 (magic div)
            unsigned c0 = e0 - q * 19u;             // 0..18
            unsigned mm = (sm_mask[q] | (sm_mask[q + 1] << 19)) >> c0;
            float4 x = pvs[j];
            s += softplus_f(x.x) + softplus_f(x.y)
               + softplus_f(x.z) + softplus_f(x.w);
            if (mm & 1u) s -= x.x;
            if (mm & 2u) s -= x.y;
            if (mm & 4u) s -= x.z;
            if (mm & 8u) s -= x.w;
        }
        __syncthreads();                 // all smem reads of this stage done

        // refill this stage with tile + NSTAGE*GRID
        unsigned nt = tile + NSTAGE * GRID;
        if (tid == 0u && nt < NTILES)
            issue_tile(tgt, preds, nt, stg, mb);
    }

    // ---- per-CTA fixed-tree reduction -> double partial ----
#pragma unroll
    for (int o = 16; o > 0; o >>= 1)
        s += __shfl_xor_sync(0xffffffffu, s, o);
    if (lane == 0u) ws[wix] = s;
    __syncthreads();
    if (tid < 32u) {
        float v = (tid < 8u) ? ws[tid] : 0.0f;
#pragma unroll
        for (int o = 4; o > 0; o >>= 1)
            v += __shfl_xor_sync(0xffffffffu, v, o);
        if (tid == 0u) {
            g_partials[cta] = (double)v;
            __threadfence();
            unsigned done = atomicAdd(&g_count, 1u);
            ws[0] = (done == (unsigned)(GRID - 1)) ? 1.0f : 0.0f;
        }
    }
    __syncthreads();
    if (ws[0] == 0.0f) return;

    // ---- Last CTA: deterministic final reduction over CTA partials ----
    double d = 0.0;
    for (unsigned i = tid; i < (unsigned)GRID; i += 256u)
        d += g_partials[i];
    sh[tid] = d;
    __syncthreads();
#pragma unroll
    for (int o = 128; o > 0; o >>= 1) {
        if (tid < (unsigned)o) sh[tid] += sh[tid + o];
        __syncthreads();
    }
    if (tid == 0) {
        out[0] = (float)(sh[0] / ((double)NB * (double)NC));
        g_count = 0;                     // reset for next graph replay
    }
}

// ---------------------------------------------------------------------------
extern "C" void kernel_launch(void* const* d_in, const int* in_sizes, int n_in,
                              void* d_out, int out_size)
{
    const float* preds = (const float*)d_in[0];
    const int*   tgt   = (const int*)d_in[1];
    // d_in[2] = grid_size (always 8 for this problem's shapes)

    static int smem_set = 0;
    if (!smem_set) {
        cudaFuncSetAttribute(fused_kernel,
                             cudaFuncAttributeMaxDynamicSharedMemorySize,
                             NSTAGE * STAGE_BYTES);
        smem_set = 1;
    }
    fused_kernel<<<GRID, 256, NSTAGE * STAGE_BYTES>>>(tgt, preds, (float*)d_out);
}